// round 2
// baseline (speedup 1.0000x reference)
#include <cuda_runtime.h>

// Problem constants
#define TT 512
#define DD 16
#define HH 48
#define NB 16         // batch per CTA
#define NBI 4         // batch per thread
#define NTHREADS 192
#define NCTA 128

// SMEM byte offsets
#define W1I_B 0                          // [16][48][4] float   (k, j, gate)
#define W1R_B (W1I_B + DD*HH*4*4)        // [48][48][4]
#define W2I_B (W1R_B + HH*HH*4*4)
#define W2R_B (W2I_B + HH*HH*4*4)
#define B1_B  (W2R_B + HH*HH*4*4)        // [48][4]
#define B2_B  (B1_B + HH*4*4)
#define H1_B  (B2_B + HH*4*4)            // [2][16][48][2] float (dup'd)
#define H2_B  (H1_B + 2*NB*HH*2*4)
#define XD_B  (H2_B + 2*NB*HH*2*4)       // [2][16][16][2] float (dup'd)
#define SMEM_BYTES (XD_B + 2*NB*DD*2*4)

#define HBUF_STRIDE (NB*HH*2*4)          // 6144 B per h buffer
#define XBUF_STRIDE (NB*DD*2*4)          // 2048 B per x buffer

__device__ __forceinline__ float fsig(float x) {
    return __fdividef(1.0f, 1.0f + __expf(-x));
}
__device__ __forceinline__ float ftanh_(float x) {
    return __fdividef(2.0f, 1.0f + __expf(-2.0f * x)) - 1.0f;
}

// packed dual-fp32 FMA: a.{lo,hi} += w.{lo,hi} * h.{lo,hi}
__device__ __forceinline__ void ffma2(unsigned long long& a,
                                      unsigned long long w,
                                      unsigned long long h) {
    asm("fma.rn.f32x2 %0, %1, %2, %0;" : "+l"(a) : "l"(w), "l"(h));
}
__device__ __forceinline__ float2 unpk(unsigned long long v) {
    float2 r;
    asm("mov.b64 {%0, %1}, %2;" : "=f"(r.x), "=f"(r.y) : "l"(v));
    return r;
}
__device__ __forceinline__ void sts_dup(char* p, float v) {
    unsigned long long d;
    asm("mov.b64 %0, {%1, %1};" : "=l"(d) : "f"(v));
    *(unsigned long long*)p = d;
}

__global__ void __launch_bounds__(NTHREADS, 1)
lstm2_kernel(const float* __restrict__ x,
             const float* __restrict__ Wih0, const float* __restrict__ Whh0,
             const float* __restrict__ bih0, const float* __restrict__ bhh0,
             const float* __restrict__ Wih1, const float* __restrict__ Whh1,
             const float* __restrict__ bih1, const float* __restrict__ bhh1,
             const float* __restrict__ fcw,  const float* __restrict__ fcb,
             float* __restrict__ out)
{
    extern __shared__ char sm[];
    float* smf = (float*)sm;
    const int tid = threadIdx.x;

    // ---- weight repack: W[g*HH+j][k] -> [k][j][4g] ----
    for (int i = tid; i < DD*HH*4; i += NTHREADS) {
        int g = i & 3, jj = (i >> 2) % HH, k = i / (HH*4);
        smf[(W1I_B >> 2) + i] = Wih0[(g*HH + jj)*DD + k];
    }
    for (int i = tid; i < HH*HH*4; i += NTHREADS) {
        int g = i & 3, jj = (i >> 2) % HH, k = i / (HH*4);
        int r = (g*HH + jj)*HH + k;
        smf[(W1R_B >> 2) + i] = Whh0[r];
        smf[(W2I_B >> 2) + i] = Wih1[r];
        smf[(W2R_B >> 2) + i] = Whh1[r];
    }
    for (int i = tid; i < HH*4; i += NTHREADS) {
        int g = i & 3, jj = i >> 2;
        smf[(B1_B >> 2) + i] = bih0[g*HH + jj] + bhh0[g*HH + jj];
        smf[(B2_B >> 2) + i] = bih1[g*HH + jj] + bhh1[g*HH + jj];
    }
    // zero both h buffers (dup'd), both layers
    for (int i = tid; i < 2*NB*HH*2*2; i += NTHREADS)
        smf[(H1_B >> 2) + i] = 0.f;   // covers H1 and H2 (contiguous)

    // lane mapping: adjacent lanes share j (weight-LDS dedup), differ in group
    const int j   = (tid >> 1) % HH;
    const int grp = (tid & 1) | ((tid >= 96) ? 2 : 0);
    const int bl0 = grp * NBI;

    const float* xg = x + ((long)blockIdx.x * NB) * (long)(TT*DD);

    // stage x[0] into XD buffer 0 (dup'd)
    for (int i = tid; i < NB*DD; i += NTHREADS) {
        int b = i >> 4, d = i & 15;
        sts_dup(sm + XD_B + 0*XBUF_STRIDE + ((b*DD + d) << 3),
                xg[(long)b*(TT*DD) + 0*DD + d]);
    }
    __syncthreads();

    const ulonglong2 bp1 = *(const ulonglong2*)(sm + B1_B + (j << 4));
    const ulonglong2 bp2 = *(const ulonglong2*)(sm + B2_B + (j << 4));

    float c1[NBI] = {0.f,0.f,0.f,0.f};
    float c2[NBI] = {0.f,0.f,0.f,0.f};

    // pipelined loop: iter t computes layer1[t] and layer2[t-1]; t=TT does layer2 only
    for (int t = 0; t <= TT; ++t) {
        const int cur = t & 1, prv = cur ^ 1;

        unsigned long long a1IF[NBI], a1GO[NBI], a2IF[NBI], a2GO[NBI];
        #pragma unroll
        for (int bb = 0; bb < NBI; ++bb) {
            a1IF[bb] = bp1.x; a1GO[bb] = bp1.y;
            a2IF[bb] = bp2.x; a2GO[bb] = bp2.y;
        }

        // ===== layer1 input part: x (dup'd in SMEM), 16 k =====
        {
            const char* xb = sm + XD_B + cur*XBUF_STRIDE;
            #pragma unroll
            for (int k = 0; k < DD; k += 2) {
                const ulonglong2 w0 = *(const ulonglong2*)(sm + W1I_B + (((k  )*HH + j) << 4));
                const ulonglong2 w1 = *(const ulonglong2*)(sm + W1I_B + (((k+1)*HH + j) << 4));
                #pragma unroll
                for (int bb = 0; bb < NBI; ++bb) {
                    const ulonglong2 xv = *(const ulonglong2*)(xb + (((bl0+bb)*DD + k) << 3));
                    ffma2(a1IF[bb], w0.x, xv.x); ffma2(a1GO[bb], w0.y, xv.x);
                    ffma2(a1IF[bb], w1.x, xv.y); ffma2(a1GO[bb], w1.y, xv.y);
                }
            }
        }

        // ===== fused recurrent loop: W1R@h1[t-1], W2I@h1[t-1], W2R@h2[t-2] =====
        {
            const char* h1b = sm + H1_B + prv*HBUF_STRIDE;   // h1[t-1]
            const char* h2b = sm + H2_B + cur*HBUF_STRIDE;   // h2[t-2]
            #pragma unroll 4
            for (int k = 0; k < HH; k += 2) {
                const ulonglong2 wa0 = *(const ulonglong2*)(sm + W1R_B + (((k  )*HH + j) << 4));
                const ulonglong2 wa1 = *(const ulonglong2*)(sm + W1R_B + (((k+1)*HH + j) << 4));
                const ulonglong2 wb0 = *(const ulonglong2*)(sm + W2I_B + (((k  )*HH + j) << 4));
                const ulonglong2 wb1 = *(const ulonglong2*)(sm + W2I_B + (((k+1)*HH + j) << 4));
                const ulonglong2 wc0 = *(const ulonglong2*)(sm + W2R_B + (((k  )*HH + j) << 4));
                const ulonglong2 wc1 = *(const ulonglong2*)(sm + W2R_B + (((k+1)*HH + j) << 4));
                #pragma unroll
                for (int bb = 0; bb < NBI; ++bb) {
                    const int boff = ((bl0+bb)*HH + k) << 3;
                    const ulonglong2 h1v = *(const ulonglong2*)(h1b + boff);
                    const ulonglong2 h2v = *(const ulonglong2*)(h2b + boff);
                    ffma2(a1IF[bb], wa0.x, h1v.x); ffma2(a1GO[bb], wa0.y, h1v.x);
                    ffma2(a1IF[bb], wa1.x, h1v.y); ffma2(a1GO[bb], wa1.y, h1v.y);
                    ffma2(a2IF[bb], wb0.x, h1v.x); ffma2(a2GO[bb], wb0.y, h1v.x);
                    ffma2(a2IF[bb], wb1.x, h1v.y); ffma2(a2GO[bb], wb1.y, h1v.y);
                    ffma2(a2IF[bb], wc0.x, h2v.x); ffma2(a2GO[bb], wc0.y, h2v.x);
                    ffma2(a2IF[bb], wc1.x, h2v.y); ffma2(a2GO[bb], wc1.y, h2v.y);
                }
            }
        }

        // ===== layer1 epilogue: write h1[t] into buf[cur] =====
        if (t < TT) {
            char* h1n = sm + H1_B + cur*HBUF_STRIDE;
            #pragma unroll
            for (int bb = 0; bb < NBI; ++bb) {
                float2 pif = unpk(a1IF[bb]);
                float2 pgo = unpk(a1GO[bb]);
                float iv = fsig(pif.x), fv = fsig(pif.y);
                float gv = ftanh_(pgo.x), ov = fsig(pgo.y);
                c1[bb] = fmaf(fv, c1[bb], iv * gv);
                sts_dup(h1n + (((bl0+bb)*HH + j) << 3), ov * ftanh_(c1[bb]));
            }
        }
        // ===== layer2 epilogue: write h2[t-1] into buf[prv] =====
        if (t > 0) {
            char* h2n = sm + H2_B + prv*HBUF_STRIDE;
            #pragma unroll
            for (int bb = 0; bb < NBI; ++bb) {
                float2 pif = unpk(a2IF[bb]);
                float2 pgo = unpk(a2GO[bb]);
                float iv = fsig(pif.x), fv = fsig(pif.y);
                float gv = ftanh_(pgo.x), ov = fsig(pgo.y);
                c2[bb] = fmaf(fv, c2[bb], iv * gv);
                sts_dup(h2n + (((bl0+bb)*HH + j) << 3), ov * ftanh_(c2[bb]));
            }
        }
        // ===== stage x[t+1] (dup'd) into buf[prv] =====
        if (t + 1 < TT) {
            for (int i = tid; i < NB*DD; i += NTHREADS) {
                int b = i >> 4, d = i & 15;
                sts_dup(sm + XD_B + prv*XBUF_STRIDE + ((b*DD + d) << 3),
                        xg[(long)b*(TT*DD) + (long)(t+1)*DD + d]);
            }
        }
        __syncthreads();
    }

    // ===== final FC + sigmoid: h2[511] lives in buf[1] =====
    if (tid < NB) {
        const float* h2f = (const float*)(sm + H2_B + 1*HBUF_STRIDE + tid*HH*8);
        float acc = fcb[0];
        #pragma unroll
        for (int jj = 0; jj < HH; ++jj)
            acc = fmaf(h2f[jj*2], fcw[jj], acc);
        out[blockIdx.x * NB + tid] = fsig(acc);
    }
}

extern "C" void kernel_launch(void* const* d_in, const int* in_sizes, int n_in,
                              void* d_out, int out_size) {
    (void)in_sizes; (void)n_in; (void)out_size;
    cudaFuncSetAttribute(lstm2_kernel,
                         cudaFuncAttributeMaxDynamicSharedMemorySize, SMEM_BYTES);
    lstm2_kernel<<<NCTA, NTHREADS, SMEM_BYTES>>>(
        (const float*)d_in[0],
        (const float*)d_in[1], (const float*)d_in[2],
        (const float*)d_in[3], (const float*)d_in[4],
        (const float*)d_in[5], (const float*)d_in[6],
        (const float*)d_in[7], (const float*)d_in[8],
        (const float*)d_in[9], (const float*)d_in[10],
        (float*)d_out);
}